// round 1
// baseline (speedup 1.0000x reference)
#include <cuda_runtime.h>
#include <cstdint>

// Problem constants
#define T_STEPS 32
#define BATCH   8192
#define W_IN0   36
#define N_OUT0  18
#define N_OUT1  8

#define B_PER_BLOCK 16
#define THREADS (B_PER_BLOCK * N_OUT0)   // 288 threads, 9 warps

// Output layout: concat(spks0[T,B,18], spks1[T,B,8], mems0[T,B,18], mems1[T,B,8])
#define N0 ((size_t)T_STEPS * BATCH * N_OUT0)   // 4718592
#define N1 ((size_t)T_STEPS * BATCH * N_OUT1)   // 2097152

__global__ __launch_bounds__(THREADS, 3)
void snn_sephia_kernel(const float* __restrict__ x_in,
                       const float* __restrict__ W0,
                       const float* __restrict__ d0,
                       const float* __restrict__ W1,
                       const float* __restrict__ d1,
                       const float* __restrict__ peaks,
                       float* __restrict__ out)
{
    __shared__ float x_sh[B_PER_BLOCK * W_IN0];    // 576 floats
    __shared__ float pw_sh[B_PER_BLOCK * N_OUT0];  // 288 floats

    const int tid     = threadIdx.x;
    const int b_local = tid / N_OUT0;          // 0..15
    const int s       = tid - b_local * N_OUT0; // 0..17
    const int tile    = (s >= 9) ? 1 : 0;
    const int j       = s - tile * 9;
    const int b_glob  = blockIdx.x * B_PER_BLOCK + b_local;

    // ---- layer0 weight column in registers: V0[w] = W0[t][w][2j] - W0[t][w][2j+1]
    float v0[18];
    #pragma unroll
    for (int w = 0; w < 18; w++) {
        const float2 p = *reinterpret_cast<const float2*>(W0 + ((tile * 18 + w) * 18 + 2 * j));
        v0[w] = p.x - p.y;
    }
    const float scale0 = d0[tile * 9 + j] * 1e-4f;   // fold P_UNITY

    // ---- per-channel SEPhIA power levels (spk in {0,1} -> two values)
    // delta = SHIFT_PM / (0.5*FWHM), FWHM = wl*1e3/Q ; gamma = 10^(-ER/20) = 0.1
    const float wl      = 1550.0f + 0.8f * (float)s;
    const float fwhm_pm = wl * 1000.0f / 15000.0f;
    const float delta   = -250.0f / (0.5f * fwhm_pm);
    const float amp2    = exp10f(peaks[s] * 0.1f) * 1000.0f;  // (10^(p/10)/1000)*1e6
    const float g       = 0.1f;
    const float dd      = delta * delta;
    const float inv     = 1.0f / (1.0f + dd);
    const float re      = (g + dd) * inv;
    const float im      = delta * (1.0f - g) * inv;
    const float pw_on   = (re * re + im * im) * amp2;
    const float pw_off  = (g * g) * amp2;

    // ---- layer1 state (threads 0..127: thread = (b2, j1), 16 x 8)
    const int b2 = tid >> 3;
    const int j1 = tid & 7;
    float v1[18];
    float scale1 = 0.0f;
    if (tid < B_PER_BLOCK * N_OUT1) {
        #pragma unroll
        for (int w = 0; w < 18; w++) {
            const float2 p = *reinterpret_cast<const float2*>(W1 + (w * 16 + 2 * j1));
            v1[w] = p.x - p.y;
        }
        scale1 = d1[j1];
    }

    // ---- output pointers (advance by per-step stride)
    float* p_pw = out + (size_t)b_glob * N_OUT0 + s;                 // spks0 (= pw0)
    float* p_m0 = out + (N0 + N1) + (size_t)b_glob * N_OUT0 + s;     // mems0
    float* p_s1 = out + N0 + ((size_t)(blockIdx.x * B_PER_BLOCK + b2)) * N_OUT1 + j1;   // spks1
    float* p_m1 = p_s1 + (N0 + N1);                                  // mems1
    const int str0 = BATCH * N_OUT0;   // 147456
    const int str1 = BATCH * N_OUT1;   // 65536

    float mem0 = 0.0f, mem1 = 0.0f;

    const float* xp = x_sh + b_local * W_IN0 + tile * 18;
    const float* pp = pw_sh + b2 * N_OUT0;

    for (int t = 0; t < T_STEPS; t++) {
        // ---- stage x tile for 16 rows (576 floats = 144 float4, coalesced)
        if (tid < (B_PER_BLOCK * W_IN0) / 4) {
            const float4 v = *reinterpret_cast<const float4*>(
                x_in + ((size_t)t * BATCH + (size_t)blockIdx.x * B_PER_BLOCK) * W_IN0 + tid * 4);
            reinterpret_cast<float4*>(x_sh)[tid] = v;
        }
        __syncthreads();

        // ---- layer0: 18-long dot, LIF (zero reset, reset from incoming mem)
        float acc = 0.0f;
        #pragma unroll
        for (int k = 0; k < 9; k++) {
            const float2 xv = reinterpret_cast<const float2*>(xp)[k];
            acc = fmaf(xv.x, v0[2 * k], acc);
            acc = fmaf(xv.y, v0[2 * k + 1], acc);
        }
        const float cur0 = acc * scale0;
        mem0 = (mem0 > 0.55f) ? 0.0f : fmaf(0.95f, mem0, cur0);
        const bool spk0 = (mem0 > 0.55f);
        const float pw = spk0 ? pw_on : pw_off;

        pw_sh[tid] = pw;
        *p_pw = pw;   p_pw += str0;
        *p_m0 = mem0; p_m0 += str0;
        __syncthreads();

        // ---- layer1 on threads 0..127 only (5 of 9 warps issue nothing here)
        if (tid < B_PER_BLOCK * N_OUT1) {
            float acc1 = 0.0f;
            #pragma unroll
            for (int k = 0; k < 9; k++) {
                const float2 pv = reinterpret_cast<const float2*>(pp)[k];
                acc1 = fmaf(pv.x, v1[2 * k], acc1);
                acc1 = fmaf(pv.y, v1[2 * k + 1], acc1);
            }
            const float cur1 = acc1 * scale1;
            mem1 = (mem1 > 0.25f) ? 0.0f : fmaf(0.95f, mem1, cur1);
            *p_s1 = (mem1 > 0.25f) ? 1.0f : 0.0f; p_s1 += str1;
            *p_m1 = mem1;                         p_m1 += str1;
        }
    }
}

extern "C" void kernel_launch(void* const* d_in, const int* in_sizes, int n_in,
                              void* d_out, int out_size)
{
    const float* x_in  = (const float*)d_in[0];  // [32, 8192, 36]
    const float* W0    = (const float*)d_in[1];  // [2, 18, 18]
    const float* d0    = (const float*)d_in[2];  // [2, 9]
    const float* W1    = (const float*)d_in[3];  // [1, 18, 16]
    const float* d1    = (const float*)d_in[4];  // [1, 8]
    const float* peaks = (const float*)d_in[5];  // [36]
    float* out = (float*)d_out;

    const int blocks = BATCH / B_PER_BLOCK;   // 512
    snn_sephia_kernel<<<blocks, THREADS>>>(x_in, W0, d0, W1, d1, peaks, out);
}

// round 6
// speedup vs baseline: 2.2940x; 2.2940x over previous
#include <cuda_runtime.h>
#include <cstdint>

// Problem constants
#define T_STEPS 32
#define BATCH   8192
#define W_IN0   36
#define N_OUT0  18
#define N_OUT1  8

#define B_PER_BLOCK 16
#define THREADS (B_PER_BLOCK * N_OUT0)   // 288 threads, 9 warps

// x tile: 32 steps * 16 rows * 36 floats
#define X_TILE_FLOATS (T_STEPS * B_PER_BLOCK * W_IN0)   // 18432
#define X_TILE_VEC4   (X_TILE_FLOATS / 4)               // 4608
#define VEC4_PER_T    (B_PER_BLOCK * W_IN0 / 4)         // 144
#define PRELOAD_ITERS (X_TILE_VEC4 / THREADS)           // 16

// Output layout: concat(spks0[T,B,18], spks1[T,B,8], mems0[T,B,18], mems1[T,B,8])
#define N0 ((size_t)T_STEPS * BATCH * N_OUT0)   // 4718592
#define N1 ((size_t)T_STEPS * BATCH * N_OUT1)   // 2097152

// dynamic smem: x tile (18432 f) + double-buffered pw (2*288 f) = 76032 B
#define SMEM_BYTES ((X_TILE_FLOATS + 2 * THREADS) * 4)

__global__ __launch_bounds__(THREADS, 3)
void snn_sephia_kernel(const float* __restrict__ x_in,
                       const float* __restrict__ W0,
                       const float* __restrict__ d0,
                       const float* __restrict__ W1,
                       const float* __restrict__ d1,
                       const float* __restrict__ peaks,
                       float* __restrict__ out)
{
    extern __shared__ float smem[];
    float* x_sh  = smem;                    // [32][576]
    float* pw_sh = smem + X_TILE_FLOATS;    // [2][288]

    const int tid     = threadIdx.x;
    const int b_local = tid / N_OUT0;           // 0..15
    const int s       = tid - b_local * N_OUT0; // 0..17
    const int tile    = (s >= 9) ? 1 : 0;
    const int j       = s - tile * 9;
    const int b_glob  = blockIdx.x * B_PER_BLOCK + b_local;

    // ---- preload the whole x tile with deep MLP (16 outstanding LDG.128/thread)
    {
        const size_t row_base = (size_t)blockIdx.x * B_PER_BLOCK * W_IN0;
        float4 v[PRELOAD_ITERS];
        #pragma unroll
        for (int it = 0; it < PRELOAD_ITERS; it++) {
            const int i   = tid + it * THREADS;
            const int t   = i / VEC4_PER_T;
            const int off = i - t * VEC4_PER_T;
            v[it] = *reinterpret_cast<const float4*>(
                x_in + (size_t)t * (BATCH * W_IN0) + row_base + off * 4);
        }
        #pragma unroll
        for (int it = 0; it < PRELOAD_ITERS; it++)
            reinterpret_cast<float4*>(x_sh)[tid + it * THREADS] = v[it];
    }

    // ---- layer0 weight column in registers: V0[w] = W0[t][w][2j] - W0[t][w][2j+1]
    float v0[18];
    #pragma unroll
    for (int w = 0; w < 18; w++) {
        const float2 p = *reinterpret_cast<const float2*>(W0 + ((tile * 18 + w) * 18 + 2 * j));
        v0[w] = p.x - p.y;
    }
    const float scale0 = d0[tile * 9 + j] * 1e-4f;   // fold P_UNITY

    // ---- per-channel SEPhIA power levels (spk in {0,1} -> two values)
    const float wl      = 1550.0f + 0.8f * (float)s;
    const float fwhm_pm = wl * 1000.0f / 15000.0f;
    const float delta   = -250.0f / (0.5f * fwhm_pm);
    const float amp2    = exp10f(peaks[s] * 0.1f) * 1000.0f;
    const float g       = 0.1f;
    const float dd      = delta * delta;
    const float inv     = 1.0f / (1.0f + dd);
    const float re      = (g + dd) * inv;
    const float im      = delta * (1.0f - g) * inv;
    const float pw_on   = (re * re + im * im) * amp2;
    const float pw_off  = (g * g) * amp2;

    // ---- layer1 state (threads 0..127: thread = (b2, j1), 16 x 8)
    const int b2 = tid >> 3;
    const int j1 = tid & 7;
    float v1[18];
    float scale1 = 0.0f;
    if (tid < B_PER_BLOCK * N_OUT1) {
        #pragma unroll
        for (int w = 0; w < 18; w++) {
            const float2 p = *reinterpret_cast<const float2*>(W1 + (w * 16 + 2 * j1));
            v1[w] = p.x - p.y;
        }
        scale1 = d1[j1];
    }

    // ---- output pointers
    float* p_pw = out + (size_t)b_glob * N_OUT0 + s;                 // spks0 (= pw0)
    float* p_m0 = out + (N0 + N1) + (size_t)b_glob * N_OUT0 + s;     // mems0
    float* p_s1 = out + N0 + ((size_t)(blockIdx.x * B_PER_BLOCK + b2)) * N_OUT1 + j1;  // spks1
    float* p_m1 = p_s1 + (N0 + N1);                                  // mems1
    const int str0 = BATCH * N_OUT0;   // 147456
    const int str1 = BATCH * N_OUT1;   // 65536

    float mem0 = 0.0f, mem1 = 0.0f;

    const int xoff = b_local * W_IN0 + tile * 18;
    const int poff = b2 * N_OUT0;

    __syncthreads();   // preload visible

    for (int t = 0; t < T_STEPS; t++) {
        // ---- layer0: 18-long dot from SMEM, LIF (zero reset, reset from incoming mem)
        const float* xp = x_sh + t * (B_PER_BLOCK * W_IN0) + xoff;
        float acc = 0.0f;
        #pragma unroll
        for (int k = 0; k < 9; k++) {
            const float2 xv = reinterpret_cast<const float2*>(xp)[k];
            acc = fmaf(xv.x, v0[2 * k], acc);
            acc = fmaf(xv.y, v0[2 * k + 1], acc);
        }
        const float cur0 = acc * scale0;
        mem0 = (mem0 > 0.55f) ? 0.0f : fmaf(0.95f, mem0, cur0);
        const float pw = (mem0 > 0.55f) ? pw_on : pw_off;

        float* pwb = pw_sh + (t & 1) * THREADS;
        pwb[tid] = pw;
        *p_pw = pw;   p_pw += str0;
        *p_m0 = mem0; p_m0 += str0;
        __syncthreads();   // single barrier per step (pw double-buffered)

        // ---- layer1 on threads 0..127 only
        if (tid < B_PER_BLOCK * N_OUT1) {
            const float* pp = pwb + poff;
            float acc1 = 0.0f;
            #pragma unroll
            for (int k = 0; k < 9; k++) {
                const float2 pv = reinterpret_cast<const float2*>(pp)[k];
                acc1 = fmaf(pv.x, v1[2 * k], acc1);
                acc1 = fmaf(pv.y, v1[2 * k + 1], acc1);
            }
            const float cur1 = acc1 * scale1;
            mem1 = (mem1 > 0.25f) ? 0.0f : fmaf(0.95f, mem1, cur1);
            *p_s1 = (mem1 > 0.25f) ? 1.0f : 0.0f; p_s1 += str1;
            *p_m1 = mem1;                         p_m1 += str1;
        }
    }
}

extern "C" void kernel_launch(void* const* d_in, const int* in_sizes, int n_in,
                              void* d_out, int out_size)
{
    const float* x_in  = (const float*)d_in[0];  // [32, 8192, 36]
    const float* W0    = (const float*)d_in[1];  // [2, 18, 18]
    const float* d0    = (const float*)d_in[2];  // [2, 9]
    const float* W1    = (const float*)d_in[3];  // [1, 18, 16]
    const float* d1    = (const float*)d_in[4];  // [1, 8]
    const float* peaks = (const float*)d_in[5];  // [36]
    float* out = (float*)d_out;

    cudaFuncSetAttribute(snn_sephia_kernel,
                         cudaFuncAttributeMaxDynamicSharedMemorySize, SMEM_BYTES);

    const int blocks = BATCH / B_PER_BLOCK;   // 512
    snn_sephia_kernel<<<blocks, THREADS, SMEM_BYTES>>>(x_in, W0, d0, W1, d1, peaks, out);
}

// round 8
// speedup vs baseline: 2.4511x; 1.0685x over previous
#include <cuda_runtime.h>
#include <cstdint>

// Problem constants
#define T_STEPS 32
#define BATCH   8192
#define W_IN0   36
#define N_OUT0  18
#define N_OUT1  8

#define B_PER_BLOCK 16
#define THREADS (B_PER_BLOCK * N_OUT0)   // 288 threads, 9 warps

// Chunked x staging: 8 steps per chunk, double buffered
#define CHUNK       8
#define NCHUNK      (T_STEPS / CHUNK)                    // 4
#define CH_FLOATS   (CHUNK * B_PER_BLOCK * W_IN0)        // 4608
#define CH_VEC4     (CH_FLOATS / 4)                      // 1152
#define VEC4_PER_T  (B_PER_BLOCK * W_IN0 / 4)            // 144
#define CP_ITERS    (CH_VEC4 / THREADS)                  // 4

// smem layout (floats): x[2][4608] | pw[2][288] | v1s[8][18]
#define SM_X        0
#define SM_PW       (2 * CH_FLOATS)                      // 9216
#define SM_V1       (SM_PW + 2 * THREADS)                // 9792
#define SMEM_FLOATS (SM_V1 + N_OUT1 * N_OUT0)            // 9936
#define SMEM_BYTES  (SMEM_FLOATS * 4)                    // 39744

// Output layout: concat(spks0[T,B,18], spks1[T,B,8], mems0[T,B,18], mems1[T,B,8])
#define N0 ((size_t)T_STEPS * BATCH * N_OUT0)
#define N1 ((size_t)T_STEPS * BATCH * N_OUT1)

#define CP_ASYNC16(dst_smem_u32, src_gen) \
    asm volatile("cp.async.cg.shared.global [%0], [%1], 16;\n" \
                 :: "r"(dst_smem_u32), "l"(src_gen) : "memory")
#define CP_COMMIT()  asm volatile("cp.async.commit_group;\n" ::: "memory")
#define CP_WAIT1()   asm volatile("cp.async.wait_group 1;\n" ::: "memory")

__global__ __launch_bounds__(THREADS, 4)
void snn_sephia_kernel(const float* __restrict__ x_in,
                       const float* __restrict__ W0,
                       const float* __restrict__ d0,
                       const float* __restrict__ W1,
                       const float* __restrict__ d1,
                       const float* __restrict__ peaks,
                       float* __restrict__ out)
{
    extern __shared__ float smem[];
    float* x_sh  = smem + SM_X;     // [2][8][576]
    float* pw_sh = smem + SM_PW;    // [2][288]
    float* v1_sh = smem + SM_V1;    // [8][18]  (j1-major, contiguous in k)

    const int tid     = threadIdx.x;
    const int b_local = tid / N_OUT0;           // 0..15
    const int s       = tid - b_local * N_OUT0; // 0..17
    const int tile    = (s >= 9) ? 1 : 0;
    const int j       = s - tile * 9;
    const int b_glob  = blockIdx.x * B_PER_BLOCK + b_local;

    const uint32_t smx = (uint32_t)__cvta_generic_to_shared(x_sh);
    const size_t row_base = (size_t)blockIdx.x * B_PER_BLOCK * W_IN0;

    // ---- issue cp.async for chunks 0 and 1 (double-buffer prologue)
    #pragma unroll
    for (int c = 0; c < 2; c++) {
        #pragma unroll
        for (int it = 0; it < CP_ITERS; it++) {
            const int i   = tid + it * THREADS;       // 0..1151
            const int tl  = i / VEC4_PER_T;           // 0..7
            const int off = i - tl * VEC4_PER_T;
            const float* src = x_in + (size_t)(c * CHUNK + tl) * (BATCH * W_IN0)
                                    + row_base + off * 4;
            CP_ASYNC16(smx + (uint32_t)(c * CH_FLOATS + i * 4) * 4u, src);
        }
        CP_COMMIT();
    }

    // ---- layer0 weight column in registers: V0[w] = W0[t][w][2j] - W0[t][w][2j+1]
    float v0[18];
    #pragma unroll
    for (int w = 0; w < 18; w++) {
        const float2 p = *reinterpret_cast<const float2*>(W0 + ((tile * 18 + w) * 18 + 2 * j));
        v0[w] = p.x - p.y;
    }
    const float scale0 = d0[tile * 9 + j] * 1e-4f;   // fold P_UNITY

    // ---- folded layer1 weights into smem: v1s[j1][k] = W1[k][2*j1] - W1[k][2*j1+1]
    if (tid < N_OUT1 * N_OUT0) {
        const int j1w = tid / N_OUT0;
        const int kw  = tid - j1w * N_OUT0;
        const float2 p = *reinterpret_cast<const float2*>(W1 + (kw * 16 + 2 * j1w));
        v1_sh[j1w * N_OUT0 + kw] = p.x - p.y;
    }

    // ---- per-channel SEPhIA power levels (spk in {0,1} -> two values)
    const float wl      = 1550.0f + 0.8f * (float)s;
    const float fwhm_pm = wl * 1000.0f / 15000.0f;
    const float delta   = -250.0f / (0.5f * fwhm_pm);
    const float amp2    = exp10f(peaks[s] * 0.1f) * 1000.0f;
    const float g       = 0.1f;
    const float dd      = delta * delta;
    const float inv     = 1.0f / (1.0f + dd);
    const float re      = (g + dd) * inv;
    const float im      = delta * (1.0f - g) * inv;
    const float pw_on   = (re * re + im * im) * amp2;
    const float pw_off  = (g * g) * amp2;

    // ---- layer1 thread mapping (threads 0..127: thread = (b2, j1), 16 x 8)
    const int b2 = tid >> 3;
    const int j1 = tid & 7;
    const float scale1 = (tid < B_PER_BLOCK * N_OUT1) ? d1[j1] : 0.0f;

    // ---- output pointers
    float* p_pw = out + (size_t)b_glob * N_OUT0 + s;                 // spks0 (= pw0)
    float* p_m0 = out + (N0 + N1) + (size_t)b_glob * N_OUT0 + s;     // mems0
    float* p_s1 = out + N0 + ((size_t)(blockIdx.x * B_PER_BLOCK + b2)) * N_OUT1 + j1;  // spks1
    float* p_m1 = p_s1 + (N0 + N1);                                  // mems1
    const int str0 = BATCH * N_OUT0;
    const int str1 = BATCH * N_OUT1;

    float mem0 = 0.0f, mem1 = 0.0f;

    const int xoff = b_local * W_IN0 + tile * 18;
    const int poff = b2 * N_OUT0;
    const float* v1p = v1_sh + j1 * N_OUT0;

    for (int c = 0; c < NCHUNK; c++) {
        CP_WAIT1();          // chunk c's copies done (chunk c+1 may be in flight)
        __syncthreads();     // all threads' copies (and v1s/pw state) visible

        const float* xc = x_sh + (c & 1) * CH_FLOATS + xoff;

        #pragma unroll
        for (int tl = 0; tl < CHUNK; tl++) {
            const int t = c * CHUNK + tl;

            // ---- layer0: 18-long dot from SMEM, LIF (zero reset, incoming-mem reset)
            const float* xp = xc + tl * (B_PER_BLOCK * W_IN0);
            float acc = 0.0f;
            #pragma unroll
            for (int k = 0; k < 9; k++) {
                const float2 xv = reinterpret_cast<const float2*>(xp)[k];
                acc = fmaf(xv.x, v0[2 * k], acc);
                acc = fmaf(xv.y, v0[2 * k + 1], acc);
            }
            const float cur0 = acc * scale0;
            mem0 = (mem0 > 0.55f) ? 0.0f : fmaf(0.95f, mem0, cur0);
            const float pw = (mem0 > 0.55f) ? pw_on : pw_off;

            float* pwb = pw_sh + (t & 1) * THREADS;
            pwb[tid] = pw;
            *p_pw = pw;   p_pw += str0;
            *p_m0 = mem0; p_m0 += str0;
            __syncthreads();   // single barrier per step (pw double-buffered)

            // ---- layer1 on threads 0..127 only
            if (tid < B_PER_BLOCK * N_OUT1) {
                const float* pp = pwb + poff;
                float acc1 = 0.0f;
                #pragma unroll
                for (int k = 0; k < 9; k++) {
                    const float2 pv = reinterpret_cast<const float2*>(pp)[k];
                    const float2 wv = reinterpret_cast<const float2*>(v1p)[k];
                    acc1 = fmaf(pv.x, wv.x, acc1);
                    acc1 = fmaf(pv.y, wv.y, acc1);
                }
                const float cur1 = acc1 * scale1;
                mem1 = (mem1 > 0.25f) ? 0.0f : fmaf(0.95f, mem1, cur1);
                *p_s1 = (mem1 > 0.25f) ? 1.0f : 0.0f; p_s1 += str1;
                *p_m1 = mem1;                         p_m1 += str1;
            }
        }

        // ---- prefetch chunk c+2 into the buffer chunk c just vacated
        if (c + 2 < NCHUNK) {
            #pragma unroll
            for (int it = 0; it < CP_ITERS; it++) {
                const int i   = tid + it * THREADS;
                const int tl2 = i / VEC4_PER_T;
                const int off = i - tl2 * VEC4_PER_T;
                const float* src = x_in + (size_t)((c + 2) * CHUNK + tl2) * (BATCH * W_IN0)
                                        + row_base + off * 4;
                CP_ASYNC16(smx + (uint32_t)((c & 1) * CH_FLOATS + i * 4) * 4u, src);
            }
            CP_COMMIT();
        }
    }
}

extern "C" void kernel_launch(void* const* d_in, const int* in_sizes, int n_in,
                              void* d_out, int out_size)
{
    const float* x_in  = (const float*)d_in[0];  // [32, 8192, 36]
    const float* W0    = (const float*)d_in[1];  // [2, 18, 18]
    const float* d0    = (const float*)d_in[2];  // [2, 9]
    const float* W1    = (const float*)d_in[3];  // [1, 18, 16]
    const float* d1    = (const float*)d_in[4];  // [1, 8]
    const float* peaks = (const float*)d_in[5];  // [36]
    float* out = (float*)d_out;

    const int blocks = BATCH / B_PER_BLOCK;   // 512
    snn_sephia_kernel<<<blocks, THREADS, SMEM_BYTES>>>(x_in, W0, d0, W1, d1, peaks, out);
}

// round 11
// speedup vs baseline: 2.4672x; 1.0066x over previous
#include <cuda_runtime.h>
#include <cstdint>

// Problem constants
#define T_STEPS 32
#define BATCH   8192
#define W_IN0   36
#define N_OUT0  18
#define N_OUT1  8

// Output layout: concat(spks0[T,B,18], spks1[T,B,8], mems0[T,B,18], mems1[T,B,8])
#define N0 ((size_t)T_STEPS * BATCH * N_OUT0)
#define N1 ((size_t)T_STEPS * BATCH * N_OUT1)

#define CHUNK  8
#define NCHUNK (T_STEPS / CHUNK)   // 4

#define CP_ASYNC16(dst_smem_u32, src_gen) \
    asm volatile("cp.async.cg.shared.global [%0], [%1], 16;\n" \
                 :: "r"(dst_smem_u32), "l"(src_gen) : "memory")
#define CP_COMMIT()  asm volatile("cp.async.commit_group;\n" ::: "memory")
#define CP_WAIT1()   asm volatile("cp.async.wait_group 1;\n" ::: "memory")
#define CP_WAIT0()   asm volatile("cp.async.wait_group 0;\n" ::: "memory")

// ======================= Kernel A: layer0 (fully independent threads) =====
#define A_ROWS       16
#define A_THREADS    (A_ROWS * N_OUT0)            // 288
#define A_CH_FLOATS  (CHUNK * A_ROWS * W_IN0)     // 4608
#define A_CH_VEC4    (A_CH_FLOATS / 4)            // 1152
#define A_VEC4_PER_T (A_ROWS * W_IN0 / 4)         // 144
#define A_CP_ITERS   (A_CH_VEC4 / A_THREADS)      // 4

__global__ __launch_bounds__(A_THREADS, 5)
void layer0_kernel(const float* __restrict__ x_in,
                   const float* __restrict__ W0,
                   const float* __restrict__ d0,
                   const float* __restrict__ peaks,
                   float* __restrict__ out)
{
    __shared__ float x_sh[2 * A_CH_FLOATS];       // 36864 B

    const int tid     = threadIdx.x;
    const int b_local = tid / N_OUT0;             // 0..15
    const int s       = tid - b_local * N_OUT0;   // 0..17
    const int tile    = (s >= 9) ? 1 : 0;
    const int j       = s - tile * 9;
    const int b_glob  = blockIdx.x * A_ROWS + b_local;

    const uint32_t smx = (uint32_t)__cvta_generic_to_shared(x_sh);
    const size_t row_base = (size_t)blockIdx.x * A_ROWS * W_IN0;

    // ---- prologue: chunks 0 and 1 in flight
    #pragma unroll
    for (int c = 0; c < 2; c++) {
        #pragma unroll
        for (int it = 0; it < A_CP_ITERS; it++) {
            const int i   = tid + it * A_THREADS;
            const int tl  = i / A_VEC4_PER_T;
            const int off = i - tl * A_VEC4_PER_T;
            const float* src = x_in + (size_t)(c * CHUNK + tl) * (BATCH * W_IN0)
                                    + row_base + off * 4;
            CP_ASYNC16(smx + (uint32_t)(c * A_CH_FLOATS + i * 4) * 4u, src);
        }
        CP_COMMIT();
    }

    // ---- folded weight column (UNSCALED — R8 bit-exact order):
    // v0[w] = W0[tile][w][2j] - W0[tile][w][2j+1]
    float v0[18];
    #pragma unroll
    for (int w = 0; w < 18; w++) {
        const float2 p = *reinterpret_cast<const float2*>(W0 + ((tile * 18 + w) * 18 + 2 * j));
        v0[w] = p.x - p.y;
    }
    const float scale0 = d0[tile * 9 + j] * 1e-4f;   // applied once after the dot

    // ---- SEPhIA per-channel power levels (spk in {0,1})
    const float wl      = 1550.0f + 0.8f * (float)s;
    const float fwhm_pm = wl * 1000.0f / 15000.0f;
    const float delta   = -250.0f / (0.5f * fwhm_pm);
    const float amp2    = exp10f(peaks[s] * 0.1f) * 1000.0f;
    const float g       = 0.1f;
    const float dd      = delta * delta;
    const float inv     = 1.0f / (1.0f + dd);
    const float re      = (g + dd) * inv;
    const float im      = delta * (1.0f - g) * inv;
    const float pw_on   = (re * re + im * im) * amp2;
    const float pw_off  = (g * g) * amp2;

    float* p_pw = out + (size_t)b_glob * N_OUT0 + s;               // spks0 (= pw0)
    float* p_m0 = p_pw + (N0 + N1);                                // mems0
    const int str0 = BATCH * N_OUT0;

    float mem0 = 0.0f;
    const int xoff = b_local * W_IN0 + tile * 18;                  // even -> 8B-aligned

    #pragma unroll
    for (int c = 0; c < NCHUNK; c++) {
        if (c == NCHUNK - 1) { CP_WAIT0(); } else { CP_WAIT1(); }
        __syncthreads();     // this chunk's data visible to all threads

        const float* xc = x_sh + (c & 1) * A_CH_FLOATS + xoff;

        #pragma unroll
        for (int tl = 0; tl < CHUNK; tl++) {
            // ---- 18-long dot, EXACT R8 association: serial fmaf, x.x then x.y
            const float* xp = xc + tl * (A_ROWS * W_IN0);
            float acc = 0.0f;
            #pragma unroll
            for (int k = 0; k < 9; k++) {
                const float2 xv = reinterpret_cast<const float2*>(xp)[k];
                acc = fmaf(xv.x, v0[2 * k], acc);
                acc = fmaf(xv.y, v0[2 * k + 1], acc);
            }
            const float cur0 = acc * scale0;

            mem0 = (mem0 > 0.55f) ? 0.0f : fmaf(0.95f, mem0, cur0);
            const float pw = (mem0 > 0.55f) ? pw_on : pw_off;

            *p_pw = pw;   p_pw += str0;
            *p_m0 = mem0; p_m0 += str0;
        }

        if (c + 2 < NCHUNK) {
            // RACE FIX: all threads must finish READING buffer (c&1) before any
            // thread overwrites it with chunk c+2 (R9/R10 bug: this barrier missing).
            __syncthreads();
            #pragma unroll
            for (int it = 0; it < A_CP_ITERS; it++) {
                const int i   = tid + it * A_THREADS;
                const int tl2 = i / A_VEC4_PER_T;
                const int off = i - tl2 * A_VEC4_PER_T;
                const float* src = x_in + (size_t)((c + 2) * CHUNK + tl2) * (BATCH * W_IN0)
                                        + row_base + off * 4;
                CP_ASYNC16(smx + (uint32_t)((c & 1) * A_CH_FLOATS + i * 4) * 4u, src);
            }
            CP_COMMIT();
        }
    }
}

// ======================= Kernel B: layer1 (reads pw back from out/L2) =====
#define B_ROWS       16
#define B_THREADS    (B_ROWS * N_OUT1)            // 128
#define B_CH_FLOATS  (CHUNK * B_ROWS * N_OUT0)    // 2304
#define B_CH_VEC4    (B_CH_FLOATS / 4)            // 576
#define B_VEC4_PER_T (B_ROWS * N_OUT0 / 4)        // 72

__global__ __launch_bounds__(B_THREADS, 8)
void layer1_kernel(const float* __restrict__ d1,
                   const float* __restrict__ W1,
                   float* __restrict__ out)
{
    __shared__ float pw_sh[2 * B_CH_FLOATS];      // 18432 B

    const int tid     = threadIdx.x;
    const int r_local = tid >> 3;                 // 0..15
    const int j1      = tid & 7;                  // 0..7

    const uint32_t smx = (uint32_t)__cvta_generic_to_shared(pw_sh);
    const float* pw_src = out;                    // spks0 region == pw0 (L2-resident)
    const size_t row_base = (size_t)blockIdx.x * B_ROWS * N_OUT0;

    // ---- prologue: chunks 0 and 1 in flight
    #pragma unroll
    for (int c = 0; c < 2; c++) {
        #pragma unroll
        for (int it = 0; it < 5; it++) {
            const int i = tid + it * B_THREADS;
            if (i < B_CH_VEC4) {
                const int tl  = i / B_VEC4_PER_T;
                const int off = i - tl * B_VEC4_PER_T;
                const float* src = pw_src + (size_t)(c * CHUNK + tl) * (BATCH * N_OUT0)
                                          + row_base + off * 4;
                CP_ASYNC16(smx + (uint32_t)(c * B_CH_FLOATS + i * 4) * 4u, src);
            }
        }
        CP_COMMIT();
    }

    // ---- folded layer1 weights (UNSCALED — R8 bit-exact order)
    float v1[18];
    #pragma unroll
    for (int w = 0; w < 18; w++) {
        const float2 p = *reinterpret_cast<const float2*>(W1 + (w * 16 + 2 * j1));
        v1[w] = p.x - p.y;
    }
    const float scale1 = d1[j1];

    float* p_s1 = out + N0 + (size_t)blockIdx.x * (B_ROWS * N_OUT1) + tid;  // spks1
    float* p_m1 = p_s1 + (N0 + N1);                                         // mems1
    const int str1 = BATCH * N_OUT1;

    float mem1 = 0.0f;
    const int poff = r_local * N_OUT0;            // even -> 8B-aligned

    #pragma unroll
    for (int c = 0; c < NCHUNK; c++) {
        if (c == NCHUNK - 1) { CP_WAIT0(); } else { CP_WAIT1(); }
        __syncthreads();     // this chunk's data visible to all threads

        const float* pc = pw_sh + (c & 1) * B_CH_FLOATS + poff;

        #pragma unroll
        for (int tl = 0; tl < CHUNK; tl++) {
            const float* pp = pc + tl * (B_ROWS * N_OUT0);
            float acc1 = 0.0f;
            #pragma unroll
            for (int k = 0; k < 9; k++) {
                const float2 pv = reinterpret_cast<const float2*>(pp)[k];
                acc1 = fmaf(pv.x, v1[2 * k], acc1);
                acc1 = fmaf(pv.y, v1[2 * k + 1], acc1);
            }
            const float cur1 = acc1 * scale1;

            mem1 = (mem1 > 0.25f) ? 0.0f : fmaf(0.95f, mem1, cur1);
            *p_s1 = (mem1 > 0.25f) ? 1.0f : 0.0f; p_s1 += str1;
            *p_m1 = mem1;                         p_m1 += str1;
        }

        if (c + 2 < NCHUNK) {
            // RACE FIX: fence reads of buffer (c&1) from the overwrite below.
            __syncthreads();
            #pragma unroll
            for (int it = 0; it < 5; it++) {
                const int i = tid + it * B_THREADS;
                if (i < B_CH_VEC4) {
                    const int tl2 = i / B_VEC4_PER_T;
                    const int off = i - tl2 * B_VEC4_PER_T;
                    const float* src = pw_src + (size_t)((c + 2) * CHUNK + tl2) * (BATCH * N_OUT0)
                                              + row_base + off * 4;
                    CP_ASYNC16(smx + (uint32_t)((c & 1) * B_CH_FLOATS + i * 4) * 4u, src);
                }
            }
            CP_COMMIT();
        }
    }
}

extern "C" void kernel_launch(void* const* d_in, const int* in_sizes, int n_in,
                              void* d_out, int out_size)
{
    const float* x_in  = (const float*)d_in[0];  // [32, 8192, 36]
    const float* W0    = (const float*)d_in[1];  // [2, 18, 18]
    const float* d0    = (const float*)d_in[2];  // [2, 9]
    const float* W1    = (const float*)d_in[3];  // [1, 18, 16]
    const float* d1    = (const float*)d_in[4];  // [1, 8]
    const float* peaks = (const float*)d_in[5];  // [36]
    float* out = (float*)d_out;

    layer0_kernel<<<BATCH / A_ROWS, A_THREADS>>>(x_in, W0, d0, peaks, out);  // 512 blocks
    layer1_kernel<<<BATCH / B_ROWS, B_THREADS>>>(d1, W1, out);               // 512 blocks
}

// round 12
// speedup vs baseline: 2.6343x; 1.0678x over previous
#include <cuda_runtime.h>
#include <cstdint>

// Problem constants
#define T_STEPS 32
#define BATCH   8192
#define W_IN0   36
#define N_OUT0  18
#define N_OUT1  8

#define B_PER_BLOCK 16
#define THREADS (B_PER_BLOCK * N_OUT0)   // 288 threads, 9 warps

// Output layout: concat(spks0[T,B,18], spks1[T,B,8], mems0[T,B,18], mems1[T,B,8])
#define N0 ((size_t)T_STEPS * BATCH * N_OUT0)
#define N1 ((size_t)T_STEPS * BATCH * N_OUT1)

#define CHUNK  8
#define NCHUNK (T_STEPS / CHUNK)   // 4

#define CH_FLOATS   (CHUNK * B_PER_BLOCK * W_IN0)   // 4608
#define CH_VEC4     (CH_FLOATS / 4)                 // 1152
#define VEC4_PER_T  (B_PER_BLOCK * W_IN0 / 4)       // 144
#define CP_ITERS    (CH_VEC4 / THREADS)             // 4

#define CP_ASYNC16(dst_smem_u32, src_gen) \
    asm volatile("cp.async.cg.shared.global [%0], [%1], 16;\n" \
                 :: "r"(dst_smem_u32), "l"(src_gen) : "memory")
#define CP_COMMIT()  asm volatile("cp.async.commit_group;\n" ::: "memory")
#define CP_WAIT1()   asm volatile("cp.async.wait_group 1;\n" ::: "memory")
#define CP_WAIT0()   asm volatile("cp.async.wait_group 0;\n" ::: "memory")

__global__ __launch_bounds__(THREADS, 4)
void snn_sephia_fused(const float* __restrict__ x_in,
                      const float* __restrict__ W0,
                      const float* __restrict__ d0,
                      const float* __restrict__ W1,
                      const float* __restrict__ d1,
                      const float* __restrict__ peaks,
                      float* __restrict__ out)
{
    __shared__ float x_sh[2 * CH_FLOATS];            // 36864 B (double-buffered x)
    __shared__ float pw_sh[CHUNK * THREADS];         //  9216 B (one chunk of pw)
    __shared__ float v1_sh[N_OUT1 * N_OUT0];         //   576 B (folded layer1 W)

    const int tid     = threadIdx.x;
    const int b_local = tid / N_OUT0;                // 0..15
    const int s       = tid - b_local * N_OUT0;      // 0..17
    const int tile    = (s >= 9) ? 1 : 0;
    const int j       = s - tile * 9;
    const int b_glob  = blockIdx.x * B_PER_BLOCK + b_local;

    const uint32_t smx = (uint32_t)__cvta_generic_to_shared(x_sh);
    const size_t row_base = (size_t)blockIdx.x * B_PER_BLOCK * W_IN0;

    // ---- prologue: x chunks 0 and 1 in flight
    #pragma unroll
    for (int c = 0; c < 2; c++) {
        #pragma unroll
        for (int it = 0; it < CP_ITERS; it++) {
            const int i   = tid + it * THREADS;
            const int tl  = i / VEC4_PER_T;
            const int off = i - tl * VEC4_PER_T;
            const float* src = x_in + (size_t)(c * CHUNK + tl) * (BATCH * W_IN0)
                                    + row_base + off * 4;
            CP_ASYNC16(smx + (uint32_t)(c * CH_FLOATS + i * 4) * 4u, src);
        }
        CP_COMMIT();
    }

    // ---- folded layer0 weight column (UNSCALED — bit-exact R8 order)
    float v0[18];
    #pragma unroll
    for (int w = 0; w < 18; w++) {
        const float2 p = *reinterpret_cast<const float2*>(W0 + ((tile * 18 + w) * 18 + 2 * j));
        v0[w] = p.x - p.y;
    }
    const float scale0 = d0[tile * 9 + j] * 1e-4f;

    // ---- folded layer1 weights into smem: v1s[j1][k] = W1[k][2j1] - W1[k][2j1+1]
    if (tid < N_OUT1 * N_OUT0) {
        const int j1w = tid / N_OUT0;
        const int kw  = tid - j1w * N_OUT0;
        const float2 p = *reinterpret_cast<const float2*>(W1 + (kw * 16 + 2 * j1w));
        v1_sh[j1w * N_OUT0 + kw] = p.x - p.y;
    }

    // ---- SEPhIA per-channel power levels (spk in {0,1})
    const float wl      = 1550.0f + 0.8f * (float)s;
    const float fwhm_pm = wl * 1000.0f / 15000.0f;
    const float delta   = -250.0f / (0.5f * fwhm_pm);
    const float amp2    = exp10f(peaks[s] * 0.1f) * 1000.0f;
    const float g       = 0.1f;
    const float dd      = delta * delta;
    const float inv     = 1.0f / (1.0f + dd);
    const float re      = (g + dd) * inv;
    const float im      = delta * (1.0f - g) * inv;
    const float pw_on   = (re * re + im * im) * amp2;
    const float pw_off  = (g * g) * amp2;

    // ---- layer1 thread mapping (threads 0..127: (b2, j1) = 16 x 8)
    const int b2 = tid >> 3;
    const int j1 = tid & 7;
    const float scale1 = (tid < B_PER_BLOCK * N_OUT1) ? d1[j1] : 0.0f;

    // ---- output pointers
    float* p_pw = out + (size_t)b_glob * N_OUT0 + s;                      // spks0 (= pw0)
    float* p_m0 = p_pw + (N0 + N1);                                       // mems0
    float* p_s1 = out + N0 + (size_t)blockIdx.x * (B_PER_BLOCK * N_OUT1) + tid;  // spks1
    float* p_m1 = p_s1 + (N0 + N1);                                       // mems1
    const int str0 = BATCH * N_OUT0;
    const int str1 = BATCH * N_OUT1;

    float mem0 = 0.0f, mem1 = 0.0f;
    const int xoff = b_local * W_IN0 + tile * 18;    // even -> 8B-aligned
    const int poff = b2 * N_OUT0;
    const float* v1p = v1_sh + j1 * N_OUT0;

    #pragma unroll
    for (int c = 0; c < NCHUNK; c++) {
        if (c == NCHUNK - 1) { CP_WAIT0(); } else { CP_WAIT1(); }
        __syncthreads();   // x chunk c visible; pw reads of chunk c-1 fenced; v1_sh ready (c=0)

        const float* xc = x_sh + (c & 1) * CH_FLOATS + xoff;

        // ---- phase 1: layer0 for 8 steps (bit-exact R8 arithmetic)
        #pragma unroll
        for (int tl = 0; tl < CHUNK; tl++) {
            const float* xp = xc + tl * (B_PER_BLOCK * W_IN0);
            float acc = 0.0f;
            #pragma unroll
            for (int k = 0; k < 9; k++) {
                const float2 xv = reinterpret_cast<const float2*>(xp)[k];
                acc = fmaf(xv.x, v0[2 * k], acc);
                acc = fmaf(xv.y, v0[2 * k + 1], acc);
            }
            const float cur0 = acc * scale0;

            mem0 = (mem0 > 0.55f) ? 0.0f : fmaf(0.95f, mem0, cur0);
            const float pw = (mem0 > 0.55f) ? pw_on : pw_off;

            pw_sh[tl * THREADS + tid] = pw;
            *p_pw = pw;   p_pw += str0;
            *p_m0 = mem0; p_m0 += str0;
        }

        __syncthreads();   // pw chunk visible; x buffer (c&1) reads done

        // ---- prefetch x chunk c+2 into the buffer just vacated (behind barrier)
        if (c + 2 < NCHUNK) {
            #pragma unroll
            for (int it = 0; it < CP_ITERS; it++) {
                const int i   = tid + it * THREADS;
                const int tl2 = i / VEC4_PER_T;
                const int off = i - tl2 * VEC4_PER_T;
                const float* src = x_in + (size_t)((c + 2) * CHUNK + tl2) * (BATCH * W_IN0)
                                        + row_base + off * 4;
                CP_ASYNC16(smx + (uint32_t)((c & 1) * CH_FLOATS + i * 4) * 4u, src);
            }
            CP_COMMIT();
        }

        // ---- phase 2: layer1 for the same 8 steps (threads 0..127 only)
        if (tid < B_PER_BLOCK * N_OUT1) {
            #pragma unroll
            for (int tl = 0; tl < CHUNK; tl++) {
                const float* pp = pw_sh + tl * THREADS + poff;
                float acc1 = 0.0f;
                #pragma unroll
                for (int k = 0; k < 9; k++) {
                    const float2 pv = reinterpret_cast<const float2*>(pp)[k];
                    const float2 wv = reinterpret_cast<const float2*>(v1p)[k];
                    acc1 = fmaf(pv.x, wv.x, acc1);
                    acc1 = fmaf(pv.y, wv.y, acc1);
                }
                const float cur1 = acc1 * scale1;

                mem1 = (mem1 > 0.25f) ? 0.0f : fmaf(0.95f, mem1, cur1);
                *p_s1 = (mem1 > 0.25f) ? 1.0f : 0.0f; p_s1 += str1;
                *p_m1 = mem1;                         p_m1 += str1;
            }
        }
        // NOTE: no barrier here. Layer1 reads of pw_sh complete before each
        // thread reaches the next chunk's entry __syncthreads(), which precedes
        // the next layer0 writes to pw_sh — single pw buffer is race-free.
    }
}

extern "C" void kernel_launch(void* const* d_in, const int* in_sizes, int n_in,
                              void* d_out, int out_size)
{
    const float* x_in  = (const float*)d_in[0];  // [32, 8192, 36]
    const float* W0    = (const float*)d_in[1];  // [2, 18, 18]
    const float* d0    = (const float*)d_in[2];  // [2, 9]
    const float* W1    = (const float*)d_in[3];  // [1, 18, 16]
    const float* d1    = (const float*)d_in[4];  // [1, 8]
    const float* peaks = (const float*)d_in[5];  // [36]
    float* out = (float*)d_out;

    // Maximize smem carveout so 4 blocks x 46.7KB fit per SM (single wave).
    cudaFuncSetAttribute(snn_sephia_fused,
                         cudaFuncAttributePreferredSharedMemoryCarveout, 100);

    snn_sephia_fused<<<BATCH / B_PER_BLOCK, THREADS>>>(x_in, W0, d0, W1, d1, peaks, out);
}